// round 4
// baseline (speedup 1.0000x reference)
#include <cuda_runtime.h>
#include <stdint.h>
#include <math.h>

#define PI_F 3.14159274101257324f

static __device__ float  g_C [512*512];
static __device__ float  g_Ct[512*512];
static __device__ float  g_T1[2*512*128];
static __device__ float4 g_G [512*512];   // {M_b0, M_b1, cosF, sinF}
static __device__ float  g_F [512*512];
static __device__ float  g_W [512*1024];  // W[j][b*512+t]
static __device__ float2 g_part[512];
static __device__ float  g_std[2];

__global__ void k_setup() {
    int k = blockIdx.x, n = threadIdx.x;
    float ang = __fmul_rn(__fmul_rn(PI_F, (float)(2*n+1)), (float)k) * (1.0f/1024.0f);
    float sk = (k == 0) ? (1.0f/sqrtf(2048.0f)) : (1.0f/sqrtf(1024.0f));
    float v = sk * (2.0f * cosf(ang));
    g_C[k*512+n] = v;
    g_Ct[n*512+k] = v;
}

__global__ void k_T1(const float* __restrict__ x) {
    int idx = blockIdx.x*256 + threadIdx.x;
    int jp = idx & 127, k = (idx>>7) & 511, b = idx>>16;
    const float* Crow = &g_C[k*512];
    const float* xb = x + b*16384 + jp;
    float acc = 0.f;
#pragma unroll 4
    for (int i = 0; i < 128; ++i) acc = fmaf(Crow[i], xb[i*128], acc);
    g_T1[b*65536 + k*128 + jp] = acc;
}

__global__ void k_M() {
    int idx = blockIdx.x*256 + threadIdx.x;
    int j = idx & 511, k = idx >> 9;
    const float* t0p = &g_T1[k*128];
    const float* t1p = &g_T1[65536 + k*128];
    float a0 = 0.f, a1 = 0.f;
#pragma unroll 4
    for (int jp = 0; jp < 128; ++jp) {
        float c = g_Ct[(128+jp)*512 + j];
        a0 = fmaf(t0p[jp], c, a0);
        a1 = fmaf(t1p[jp], c, a1);
    }
    float ak = g_C[k*512];
    float ky = __fmul_rn((float)k*(1.0f/512.0f), PI_F);
    float kx = __fmul_rn((float)j*(1.0f/512.0f), PI_F);
    float F  = sqrtf(__fadd_rn(__fmul_rn(ky,ky), __fmul_rn(kx,kx)));
    float s, c;
    sincosf(F, &s, &c);
    g_G[j*512+k] = make_float4(ak*a0, ak*a1, c, s);
    g_F[j*512+k] = F;
}

__global__ void __launch_bounds__(128) k_wave() {
    int lane = threadIdx.x, y = threadIdx.y, j = blockIdx.x;
    float t0f = (float)(lane*16);
    float acc0[16], acc1[16];
#pragma unroll
    for (int d = 0; d < 16; ++d) { acc0[d] = 0.f; acc1[d] = 0.f; }
    const float4* G = &g_G[j*512 + y*128];
    const float*  Fp = &g_F[j*512 + y*128];
    for (int kk = 0; kk < 128; ++kk) {
        float4 g = __ldg(&G[kk]);
        float F = __ldg(&Fp[kk]);
        float s, c;
        sincosf(__fmul_rn(F, t0f), &s, &c);     // exact anchor at t0
        float cF = g.z, sF = g.w;
#pragma unroll
        for (int d = 0; d < 16; ++d) {
            acc0[d] = fmaf(c, g.x, acc0[d]);
            acc1[d] = fmaf(c, g.y, acc1[d]);
            float cn = fmaf(c, cF, -(s*sF));    // rotate by F (stable for all F)
            float sn = fmaf(s, cF,   c*sF);
            c = cn; s = sn;
        }
    }
    __shared__ float sh[3][32][33];
    if (y > 0) {
#pragma unroll
        for (int d = 0; d < 16; ++d) {
            sh[y-1][lane][d]    = acc0[d];
            sh[y-1][lane][16+d] = acc1[d];
        }
    }
    __syncthreads();
    if (y == 0) {
#pragma unroll
        for (int d = 0; d < 16; ++d) {
            float a0 = acc0[d] + sh[0][lane][d]    + sh[1][lane][d]    + sh[2][lane][d];
            float a1 = acc1[d] + sh[0][lane][16+d] + sh[1][lane][16+d] + sh[2][lane][16+d];
            g_W[j*1024 +       lane*16 + d] = a0;
            g_W[j*1024 + 512 + lane*16 + d] = a1;
        }
    }
}

__global__ void __launch_bounds__(256) k_gemm(float* __restrict__ out) {
    __shared__ float As[16][64];
    __shared__ float Bs[16][64];
    int tid = threadIdx.x;
    int r0 = blockIdx.x*64, l0 = blockIdx.y*64;
    int lkk = tid >> 4, lq = tid & 15;
    int ty = tid >> 4, tx = tid & 15;
    float acc[4][4] = {};
    for (int j0 = 0; j0 < 512; j0 += 16) {
        *(float4*)&As[lkk][lq*4] = *(const float4*)&g_W[(j0+lkk)*1024 + r0 + lq*4];
        *(float4*)&Bs[lkk][lq*4] = *(const float4*)&g_C[(j0+lkk)*512  + l0 + lq*4];
        __syncthreads();
#pragma unroll
        for (int kk = 0; kk < 16; ++kk) {
            float4 av = *(const float4*)&As[kk][ty*4];
            float4 bv = *(const float4*)&Bs[kk][tx*4];
            float ar[4] = {av.x, av.y, av.z, av.w};
            float br[4] = {bv.x, bv.y, bv.z, bv.w};
#pragma unroll
            for (int i = 0; i < 4; ++i)
#pragma unroll
                for (int l = 0; l < 4; ++l)
                    acc[i][l] = fmaf(ar[i], br[l], acc[i][l]);
        }
        __syncthreads();
    }
#pragma unroll
    for (int i = 0; i < 4; ++i)
#pragma unroll
        for (int l = 0; l < 4; ++l)
            out[(r0+ty*4+i)*512 + l0+tx*4+l] = acc[i][l] * (1.0f/3.0f);
}

__global__ void k_red1(const float* __restrict__ out) {
    __shared__ float ss[256], sq[256];
    int tid = threadIdx.x;
    int base = blockIdx.x * 1024;
    float s = 0.f, q = 0.f;
#pragma unroll
    for (int i = 0; i < 4; ++i) {
        float v = out[base + i*256 + tid];
        s += v; q = fmaf(v, v, q);
    }
    ss[tid] = s; sq[tid] = q;
    __syncthreads();
    for (int st = 128; st > 0; st >>= 1) {
        if (tid < st) { ss[tid] += ss[tid+st]; sq[tid] += sq[tid+st]; }
        __syncthreads();
    }
    if (tid == 0) g_part[blockIdx.x] = make_float2(ss[0], sq[0]);
}

__global__ void k_red2() {
    __shared__ double ss[256], sq[256];
    int tid = threadIdx.x;
    for (int b = 0; b < 2; ++b) {
        float2 p = g_part[b*256 + tid];
        ss[tid] = (double)p.x; sq[tid] = (double)p.y;
        __syncthreads();
        for (int st = 128; st > 0; st >>= 1) {
            if (tid < st) { ss[tid] += ss[tid+st]; sq[tid] += sq[tid+st]; }
            __syncthreads();
        }
        if (tid == 0) {
            double n = 262144.0;
            double mean = ss[0]/n;
            double var = sq[0]/n - mean*mean;
            g_std[b] = (float)sqrt(var > 0.0 ? var : 0.0);
        }
        __syncthreads();
    }
}

__device__ __forceinline__ uint32_t rotl32(uint32_t x, int d) { return (x<<d)|(x>>(32-d)); }

__device__ __forceinline__ float tf_to_normal(uint32_t bits) {
    const float LO = -0.99999994f;
    float f = __uint_as_float((bits >> 9) | 0x3f800000u) - 1.0f;
    float u = fmaxf(LO, __fadd_rn(__fmul_rn(f, 2.0f), LO));
    return 1.41421356f * erfinvf(u);
}

// JAX partitionable threefry (default >= 0.4.30):
// counter pair = iota_2x32_shape -> (hi32(i), lo32(i)) = (0, i);
// 32-bit draw = bits1 ^ bits2 (the <64-bit branch of
// _threefry_random_bits_partitionable).
__global__ void k_noise(float* __restrict__ out) {
    uint32_t i = blockIdx.x*256 + threadIdx.x;   // 524288 threads
    uint32_t x0 = 0u, x1 = i;
    const uint32_t ks0 = 0u, ks1 = 42u, ks2 = 0x1BD11BDAu ^ 0u ^ 42u;
    x0 += ks0; x1 += ks1;
#define RND(rr) { x0 += x1; x1 = rotl32(x1, rr); x1 ^= x0; }
    RND(13) RND(15) RND(26) RND(6)   x0 += ks1; x1 += ks2 + 1u;
    RND(17) RND(29) RND(16) RND(24)  x0 += ks2; x1 += ks0 + 2u;
    RND(13) RND(15) RND(26) RND(6)   x0 += ks0; x1 += ks1 + 3u;
    RND(17) RND(29) RND(16) RND(24)  x0 += ks1; x1 += ks2 + 4u;
    RND(13) RND(15) RND(26) RND(6)   x0 += ks2; x1 += ks0 + 5u;
#undef RND
    float n = tf_to_normal(x0 ^ x1);
    uint32_t b = i >> 18;                        // 262144 per batch
    out[i] = __fadd_rn(out[i], __fmul_rn(n, g_std[b]));
}

extern "C" void kernel_launch(void* const* d_in, const int* in_sizes, int n_in,
                              void* d_out, int out_size) {
    const float* x = (const float*)d_in[0];
    float* out = (float*)d_out;
    k_setup<<<512, 512>>>();
    k_T1<<<512, 256>>>(x);
    k_M<<<1024, 256>>>();
    k_wave<<<512, dim3(32,4)>>>();
    k_gemm<<<dim3(16,8), 256>>>(out);
    k_red1<<<512, 256>>>(out);
    k_red2<<<1, 256>>>();
    k_noise<<<2048, 256>>>(out);
}

// round 5
// speedup vs baseline: 1.1690x; 1.1690x over previous
#include <cuda_runtime.h>
#include <stdint.h>
#include <math.h>

#define PI_F 3.14159274101257324f

static __device__ float  g_C [512*512];
static __device__ float  g_Ct[512*512];
static __device__ float  g_T1[2*512*128];
static __device__ float4 g_G [512*512];   // {M_b0, M_b1, cosF, sinF}
static __device__ float  g_F [512*512];
static __device__ float  g_W [512*1024];  // W[j][b*512+t]
static __device__ float2 g_part[512];
static __device__ float  g_std[2];

__global__ void k_setup() {
    int k = blockIdx.x, n = threadIdx.x;
    float ang = __fmul_rn(__fmul_rn(PI_F, (float)(2*n+1)), (float)k) * (1.0f/1024.0f);
    float sk = (k == 0) ? (1.0f/sqrtf(2048.0f)) : (1.0f/sqrtf(1024.0f));
    float v = sk * (2.0f * cosf(ang));
    g_C[k*512+n] = v;
    g_Ct[n*512+k] = v;
}

__global__ void k_T1(const float* __restrict__ x) {
    int idx = blockIdx.x*256 + threadIdx.x;
    int jp = idx & 127, k = (idx>>7) & 511, b = idx>>16;
    const float* Crow = &g_C[k*512];
    const float* xb = x + b*16384 + jp;
    float acc = 0.f;
#pragma unroll 4
    for (int i = 0; i < 128; ++i) acc = fmaf(Crow[i], xb[i*128], acc);
    g_T1[b*65536 + k*128 + jp] = acc;
}

__global__ void k_M() {
    int idx = blockIdx.x*256 + threadIdx.x;
    int j = idx & 511, k = idx >> 9;
    const float* t0p = &g_T1[k*128];
    const float* t1p = &g_T1[65536 + k*128];
    float a0 = 0.f, a1 = 0.f;
#pragma unroll 4
    for (int jp = 0; jp < 128; ++jp) {
        float c = g_Ct[(128+jp)*512 + j];
        a0 = fmaf(t0p[jp], c, a0);
        a1 = fmaf(t1p[jp], c, a1);
    }
    float ak = g_C[k*512];
    float ky = __fmul_rn((float)k*(1.0f/512.0f), PI_F);
    float kx = __fmul_rn((float)j*(1.0f/512.0f), PI_F);
    float F  = sqrtf(__fadd_rn(__fmul_rn(ky,ky), __fmul_rn(kx,kx)));
    float s, c;
    sincosf(F, &s, &c);
    g_G[j*512+k] = make_float4(ak*a0, ak*a1, c, s);
    g_F[j*512+k] = F;
}

// 256 threads: 32 t-chunk lanes x 8 k-segments of 64.
// Chebyshev cos recurrence, exact sincosf anchor + exact-spaced second seed.
__global__ void __launch_bounds__(256) k_wave() {
    int lane = threadIdx.x & 31, y = threadIdx.x >> 5, j = blockIdx.x;
    float t0f = (float)(lane*16);
    float acc0[16], acc1[16];
#pragma unroll
    for (int d = 0; d < 16; ++d) { acc0[d] = 0.f; acc1[d] = 0.f; }
    const float4* G  = &g_G[j*512 + y*64];
    const float*  Fp = &g_F[j*512 + y*64];
    for (int kk = 0; kk < 64; ++kk) {
        float4 g = __ldg(&G[kk]);
        float F  = __ldg(&Fp[kk]);
        float s, c;
        sincosf(__fmul_rn(F, t0f), &s, &c);
        float ca = c;                               // cos(F*t0), ref-exact arg
        float cb = fmaf(c, g.z, -(s*g.w));          // cos(F*t0 + F), exact spacing
        float r  = g.z + g.z;                       // 2 cos F
#pragma unroll
        for (int d = 0; d < 16; ++d) {
            acc0[d] = fmaf(ca, g.x, acc0[d]);
            acc1[d] = fmaf(ca, g.y, acc1[d]);
            float cn = fmaf(r, cb, -ca);            // Chebyshev step
            ca = cb; cb = cn;
        }
    }
    __shared__ float sh[7][32][33];
    if (y > 0) {
#pragma unroll
        for (int d = 0; d < 16; ++d) {
            sh[y-1][lane][d]    = acc0[d];
            sh[y-1][lane][16+d] = acc1[d];
        }
    }
    __syncthreads();
    if (y == 0) {
#pragma unroll
        for (int d = 0; d < 16; ++d) {
            float a0 = acc0[d], a1 = acc1[d];
#pragma unroll
            for (int q = 0; q < 7; ++q) {
                a0 += sh[q][lane][d];
                a1 += sh[q][lane][16+d];
            }
            g_W[j*1024 +       lane*16 + d] = a0;
            g_W[j*1024 + 512 + lane*16 + d] = a1;
        }
    }
}

// 64x32 output tile, 256 blocks.
__global__ void __launch_bounds__(256) k_gemm(float* __restrict__ out) {
    __shared__ float As[16][64];
    __shared__ float Bs[16][32];
    int tid = threadIdx.x;
    int r0 = blockIdx.x*64, l0 = blockIdx.y*32;
    int ty = tid >> 4, tx = tid & 15;
    float acc[4][2] = {};
    for (int j0 = 0; j0 < 512; j0 += 16) {
        *(float4*)&As[tid>>4][(tid&15)*4] =
            *(const float4*)&g_W[(j0 + (tid>>4))*1024 + r0 + (tid&15)*4];
        if (tid < 128)
            *(float4*)&Bs[tid>>3][(tid&7)*4] =
                *(const float4*)&g_C[(j0 + (tid>>3))*512 + l0 + (tid&7)*4];
        __syncthreads();
#pragma unroll
        for (int kk = 0; kk < 16; ++kk) {
            float4 av = *(const float4*)&As[kk][ty*4];
            float2 bv = *(const float2*)&Bs[kk][tx*2];
            float ar[4] = {av.x, av.y, av.z, av.w};
#pragma unroll
            for (int i = 0; i < 4; ++i) {
                acc[i][0] = fmaf(ar[i], bv.x, acc[i][0]);
                acc[i][1] = fmaf(ar[i], bv.y, acc[i][1]);
            }
        }
        __syncthreads();
    }
#pragma unroll
    for (int i = 0; i < 4; ++i) {
        out[(r0+ty*4+i)*512 + l0+tx*2    ] = acc[i][0] * (1.0f/3.0f);
        out[(r0+ty*4+i)*512 + l0+tx*2 + 1] = acc[i][1] * (1.0f/3.0f);
    }
}

__global__ void k_red1(const float* __restrict__ out) {
    __shared__ float ss[256], sq[256];
    int tid = threadIdx.x;
    int base = blockIdx.x * 1024;
    float s = 0.f, q = 0.f;
#pragma unroll
    for (int i = 0; i < 4; ++i) {
        float v = out[base + i*256 + tid];
        s += v; q = fmaf(v, v, q);
    }
    ss[tid] = s; sq[tid] = q;
    __syncthreads();
    for (int st = 128; st > 0; st >>= 1) {
        if (tid < st) { ss[tid] += ss[tid+st]; sq[tid] += sq[tid+st]; }
        __syncthreads();
    }
    if (tid == 0) g_part[blockIdx.x] = make_float2(ss[0], sq[0]);
}

__global__ void k_red2() {
    __shared__ double ss[256], sq[256];
    int tid = threadIdx.x;
    for (int b = 0; b < 2; ++b) {
        float2 p = g_part[b*256 + tid];
        ss[tid] = (double)p.x; sq[tid] = (double)p.y;
        __syncthreads();
        for (int st = 128; st > 0; st >>= 1) {
            if (tid < st) { ss[tid] += ss[tid+st]; sq[tid] += sq[tid+st]; }
            __syncthreads();
        }
        if (tid == 0) {
            double n = 262144.0;
            double mean = ss[0]/n;
            double var = sq[0]/n - mean*mean;
            g_std[b] = (float)sqrt(var > 0.0 ? var : 0.0);
        }
        __syncthreads();
    }
}

__device__ __forceinline__ uint32_t rotl32(uint32_t x, int d) { return (x<<d)|(x>>(32-d)); }

__device__ __forceinline__ float tf_to_normal(uint32_t bits) {
    const float LO = -0.99999994f;
    float f = __uint_as_float((bits >> 9) | 0x3f800000u) - 1.0f;
    float u = fmaxf(LO, __fadd_rn(__fmul_rn(f, 2.0f), LO));
    return 1.41421356f * erfinvf(u);
}

__global__ void k_noise(float* __restrict__ out) {
    uint32_t i = blockIdx.x*256 + threadIdx.x;
    uint32_t x0 = 0u, x1 = i;
    const uint32_t ks0 = 0u, ks1 = 42u, ks2 = 0x1BD11BDAu ^ 0u ^ 42u;
    x0 += ks0; x1 += ks1;
#define RND(rr) { x0 += x1; x1 = rotl32(x1, rr); x1 ^= x0; }
    RND(13) RND(15) RND(26) RND(6)   x0 += ks1; x1 += ks2 + 1u;
    RND(17) RND(29) RND(16) RND(24)  x0 += ks2; x1 += ks0 + 2u;
    RND(13) RND(15) RND(26) RND(6)   x0 += ks0; x1 += ks1 + 3u;
    RND(17) RND(29) RND(16) RND(24)  x0 += ks1; x1 += ks2 + 4u;
    RND(13) RND(15) RND(26) RND(6)   x0 += ks2; x1 += ks0 + 5u;
#undef RND
    float n = tf_to_normal(x0 ^ x1);
    uint32_t b = i >> 18;
    out[i] = __fadd_rn(out[i], __fmul_rn(n, g_std[b]));
}

extern "C" void kernel_launch(void* const* d_in, const int* in_sizes, int n_in,
                              void* d_out, int out_size) {
    const float* x = (const float*)d_in[0];
    float* out = (float*)d_out;
    k_setup<<<512, 512>>>();
    k_T1<<<512, 256>>>(x);
    k_M<<<1024, 256>>>();
    k_wave<<<512, 256>>>();
    k_gemm<<<dim3(16,16), 256>>>(out);
    k_red1<<<512, 256>>>(out);
    k_red2<<<1, 256>>>();
    k_noise<<<2048, 256>>>(out);
}

// round 6
// speedup vs baseline: 1.2685x; 1.0852x over previous
#include <cuda_runtime.h>
#include <stdint.h>
#include <math.h>

#define PI_F 3.14159274101257324f

static __device__ float  g_C [512*512];
static __device__ float  g_Ct[512*512];
static __device__ float  g_T1[2*512*128];
static __device__ float4 g_G [512*512];   // {M_b0, M_b1, cosF, sinF}
static __device__ float  g_F [512*512];
static __device__ float  g_W [512*1024];  // partial W, k in [0,256)
static __device__ float  g_W2[512*1024];  // partial W, k in [256,512)
static __device__ float2 g_part[512];
static __device__ float  g_std[2];

__global__ void k_setup() {
    int k = blockIdx.x, n = threadIdx.x;
    float ang = __fmul_rn(__fmul_rn(PI_F, (float)(2*n+1)), (float)k) * (1.0f/1024.0f);
    float sk = (k == 0) ? (1.0f/sqrtf(2048.0f)) : (1.0f/sqrtf(1024.0f));
    float v = sk * (2.0f * cosf(ang));
    g_C[k*512+n] = v;
    g_Ct[n*512+k] = v;
}

__global__ void k_T1(const float* __restrict__ x) {
    int idx = blockIdx.x*256 + threadIdx.x;
    int jp = idx & 127, k = (idx>>7) & 511, b = idx>>16;
    const float* Crow = &g_C[k*512];
    const float* xb = x + b*16384 + jp;
    float acc = 0.f;
#pragma unroll 4
    for (int i = 0; i < 128; ++i) acc = fmaf(Crow[i], xb[i*128], acc);
    g_T1[b*65536 + k*128 + jp] = acc;
}

__global__ void k_M() {
    int idx = blockIdx.x*256 + threadIdx.x;
    int j = idx & 511, k = idx >> 9;
    const float* t0p = &g_T1[k*128];
    const float* t1p = &g_T1[65536 + k*128];
    float a0 = 0.f, a1 = 0.f;
#pragma unroll 4
    for (int jp = 0; jp < 128; ++jp) {
        float c = g_Ct[(128+jp)*512 + j];
        a0 = fmaf(t0p[jp], c, a0);
        a1 = fmaf(t1p[jp], c, a1);
    }
    float ak = g_C[k*512];
    float ky = __fmul_rn((float)k*(1.0f/512.0f), PI_F);
    float kx = __fmul_rn((float)j*(1.0f/512.0f), PI_F);
    float F  = sqrtf(__fadd_rn(__fmul_rn(ky,ky), __fmul_rn(kx,kx)));
    float s, c;
    sincosf(F, &s, &c);           // full precision: feeds the recurrence constants
    g_G[j*512+k] = make_float4(ak*a0, ak*a1, c, s);
    g_F[j*512+k] = F;
}

// grid 1024: bx = j*2 + half; 256 threads = 32 t-lanes x 8 k-segments of 32.
// Chebyshev cos recurrence, fast __sincosf anchor (error ~1e-4, OK vs 1e-3).
__global__ void __launch_bounds__(256, 5) k_wave() {
    int lane = threadIdx.x & 31, y = threadIdx.x >> 5;
    int j = blockIdx.x >> 1, half = blockIdx.x & 1;
    float t0f = (float)(lane*16);
    float acc0[16], acc1[16];
#pragma unroll
    for (int d = 0; d < 16; ++d) { acc0[d] = 0.f; acc1[d] = 0.f; }
    const float4* G  = &g_G[j*512 + half*256 + y*32];
    const float*  Fp = &g_F[j*512 + half*256 + y*32];
    for (int kk = 0; kk < 32; ++kk) {
        float4 g = __ldg(&G[kk]);
        float F  = __ldg(&Fp[kk]);
        float s, c;
        __sincosf(__fmul_rn(F, t0f), &s, &c);
        float ca = c;
        float cb = fmaf(c, g.z, -(s*g.w));          // cos(F*t0 + F), exact spacing
        float r  = g.z + g.z;
#pragma unroll
        for (int d = 0; d < 16; ++d) {
            acc0[d] = fmaf(ca, g.x, acc0[d]);
            acc1[d] = fmaf(ca, g.y, acc1[d]);
            float cn = fmaf(r, cb, -ca);
            ca = cb; cb = cn;
        }
    }
    __shared__ float sh[7][32][33];
    if (y > 0) {
#pragma unroll
        for (int d = 0; d < 16; ++d) {
            sh[y-1][lane][d]    = acc0[d];
            sh[y-1][lane][16+d] = acc1[d];
        }
    }
    __syncthreads();
    if (y == 0) {
        float* Wp = half ? g_W2 : g_W;
#pragma unroll
        for (int d = 0; d < 16; ++d) {
            float a0 = acc0[d], a1 = acc1[d];
#pragma unroll
            for (int q = 0; q < 7; ++q) {
                a0 += sh[q][lane][d];
                a1 += sh[q][lane][16+d];
            }
            Wp[j*1024 +       lane*16 + d] = a0;
            Wp[j*1024 + 512 + lane*16 + d] = a1;
        }
    }
}

__global__ void __launch_bounds__(256) k_gemm(float* __restrict__ out) {
    __shared__ float As[16][64];
    __shared__ float Bs[16][32];
    int tid = threadIdx.x;
    int r0 = blockIdx.x*64, l0 = blockIdx.y*32;
    int ty = tid >> 4, tx = tid & 15;
    float acc[4][2] = {};
    for (int j0 = 0; j0 < 512; j0 += 16) {
        {
            int off = (j0 + (tid>>4))*1024 + r0 + (tid&15)*4;
            float4 wa = *(const float4*)&g_W [off];
            float4 wb = *(const float4*)&g_W2[off];
            float4 w = make_float4(wa.x+wb.x, wa.y+wb.y, wa.z+wb.z, wa.w+wb.w);
            *(float4*)&As[tid>>4][(tid&15)*4] = w;
        }
        if (tid < 128)
            *(float4*)&Bs[tid>>3][(tid&7)*4] =
                *(const float4*)&g_C[(j0 + (tid>>3))*512 + l0 + (tid&7)*4];
        __syncthreads();
#pragma unroll
        for (int kk = 0; kk < 16; ++kk) {
            float4 av = *(const float4*)&As[kk][ty*4];
            float2 bv = *(const float2*)&Bs[kk][tx*2];
            float ar[4] = {av.x, av.y, av.z, av.w};
#pragma unroll
            for (int i = 0; i < 4; ++i) {
                acc[i][0] = fmaf(ar[i], bv.x, acc[i][0]);
                acc[i][1] = fmaf(ar[i], bv.y, acc[i][1]);
            }
        }
        __syncthreads();
    }
#pragma unroll
    for (int i = 0; i < 4; ++i) {
        out[(r0+ty*4+i)*512 + l0+tx*2    ] = acc[i][0] * (1.0f/3.0f);
        out[(r0+ty*4+i)*512 + l0+tx*2 + 1] = acc[i][1] * (1.0f/3.0f);
    }
}

__global__ void k_red1(const float* __restrict__ out) {
    __shared__ float ss[256], sq[256];
    int tid = threadIdx.x;
    int base = blockIdx.x * 1024;
    float s = 0.f, q = 0.f;
#pragma unroll
    for (int i = 0; i < 4; ++i) {
        float v = out[base + i*256 + tid];
        s += v; q = fmaf(v, v, q);
    }
    ss[tid] = s; sq[tid] = q;
    __syncthreads();
    for (int st = 128; st > 0; st >>= 1) {
        if (tid < st) { ss[tid] += ss[tid+st]; sq[tid] += sq[tid+st]; }
        __syncthreads();
    }
    if (tid == 0) g_part[blockIdx.x] = make_float2(ss[0], sq[0]);
}

__global__ void k_red2() {
    __shared__ double ss[256], sq[256];
    int tid = threadIdx.x;
    for (int b = 0; b < 2; ++b) {
        float2 p = g_part[b*256 + tid];
        ss[tid] = (double)p.x; sq[tid] = (double)p.y;
        __syncthreads();
        for (int st = 128; st > 0; st >>= 1) {
            if (tid < st) { ss[tid] += ss[tid+st]; sq[tid] += sq[tid+st]; }
            __syncthreads();
        }
        if (tid == 0) {
            double n = 262144.0;
            double mean = ss[0]/n;
            double var = sq[0]/n - mean*mean;
            g_std[b] = (float)sqrt(var > 0.0 ? var : 0.0);
        }
        __syncthreads();
    }
}

__device__ __forceinline__ uint32_t rotl32(uint32_t x, int d) { return (x<<d)|(x>>(32-d)); }

__device__ __forceinline__ float tf_to_normal(uint32_t bits) {
    const float LO = -0.99999994f;
    float f = __uint_as_float((bits >> 9) | 0x3f800000u) - 1.0f;
    float u = fmaxf(LO, __fadd_rn(__fmul_rn(f, 2.0f), LO));
    return 1.41421356f * erfinvf(u);
}

__global__ void k_noise(float* __restrict__ out) {
    uint32_t i = blockIdx.x*256 + threadIdx.x;
    uint32_t x0 = 0u, x1 = i;
    const uint32_t ks0 = 0u, ks1 = 42u, ks2 = 0x1BD11BDAu ^ 0u ^ 42u;
    x0 += ks0; x1 += ks1;
#define RND(rr) { x0 += x1; x1 = rotl32(x1, rr); x1 ^= x0; }
    RND(13) RND(15) RND(26) RND(6)   x0 += ks1; x1 += ks2 + 1u;
    RND(17) RND(29) RND(16) RND(24)  x0 += ks2; x1 += ks0 + 2u;
    RND(13) RND(15) RND(26) RND(6)   x0 += ks0; x1 += ks1 + 3u;
    RND(17) RND(29) RND(16) RND(24)  x0 += ks1; x1 += ks2 + 4u;
    RND(13) RND(15) RND(26) RND(6)   x0 += ks2; x1 += ks0 + 5u;
#undef RND
    float n = tf_to_normal(x0 ^ x1);
    uint32_t b = i >> 18;
    out[i] = __fadd_rn(out[i], __fmul_rn(n, g_std[b]));
}

extern "C" void kernel_launch(void* const* d_in, const int* in_sizes, int n_in,
                              void* d_out, int out_size) {
    const float* x = (const float*)d_in[0];
    float* out = (float*)d_out;
    k_setup<<<512, 512>>>();
    k_T1<<<512, 256>>>(x);
    k_M<<<1024, 256>>>();
    k_wave<<<1024, 256>>>();
    k_gemm<<<dim3(16,16), 256>>>(out);
    k_red1<<<512, 256>>>(out);
    k_red2<<<1, 256>>>();
    k_noise<<<2048, 256>>>(out);
}